// round 14
// baseline (speedup 1.0000x reference)
#include <cuda_runtime.h>
#include <cuda_fp16.h>
#include <stdint.h>

// Problem constants
#define BB 8
#define TT 4096
#define CC 1024
#define DD 64

#define PS 72  // padded smem row stride (halves): 144B -> conflict-free ldmatrix

// Projected tensors (fp16), row-major [b*T + t][d]. Q is pre-scaled by
// (1/8)*log2(e) so softmax is exp2 of the raw S accumulator.
__device__ __align__(16) __half g_Qh[BB * TT * DD];
__device__ __align__(16) __half g_Kh[BB * TT * DD];
__device__ __align__(16) __half g_Vh[BB * TT * DD];
// Fused weights fp16: rows 0-63 Wq, 64-127 Wk, 128-191 Wv
__device__ __align__(16) __half g_Wh[192 * CC];

// ---------------------------------------------------------------------------
// Warp-mma + cp.async helpers (sm_80+ ISA: works on base sm_103 target)
// ---------------------------------------------------------------------------
__device__ __forceinline__ uint32_t smem_u32(const void* p) {
    uint32_t a;
    asm("{ .reg .u64 t; cvta.to.shared.u64 t, %1; cvt.u32.u64 %0, t; }"
        : "=r"(a) : "l"(p));
    return a;
}
__device__ __forceinline__ void ldsm_x4(uint32_t* r, uint32_t a) {
    asm volatile("ldmatrix.sync.aligned.m8n8.x4.shared.b16 {%0,%1,%2,%3}, [%4];"
                 : "=r"(r[0]), "=r"(r[1]), "=r"(r[2]), "=r"(r[3]) : "r"(a));
}
__device__ __forceinline__ void ldsm_x4_t(uint32_t* r, uint32_t a) {
    asm volatile("ldmatrix.sync.aligned.m8n8.x4.trans.shared.b16 {%0,%1,%2,%3}, [%4];"
                 : "=r"(r[0]), "=r"(r[1]), "=r"(r[2]), "=r"(r[3]) : "r"(a));
}
__device__ __forceinline__ void mma16816(float* c, const uint32_t* a, const uint32_t* b) {
    asm volatile(
        "mma.sync.aligned.m16n8k16.row.col.f32.f16.f16.f32 "
        "{%0,%1,%2,%3}, {%4,%5,%6,%7}, {%8,%9}, {%0,%1,%2,%3};"
        : "+f"(c[0]), "+f"(c[1]), "+f"(c[2]), "+f"(c[3])
        : "r"(a[0]), "r"(a[1]), "r"(a[2]), "r"(a[3]), "r"(b[0]), "r"(b[1]));
}
__device__ __forceinline__ uint32_t pack_h2(float a, float b) {
    __half2 h = __floats2half2_rn(a, b);
    return *(uint32_t*)&h;
}
__device__ __forceinline__ uint32_t ex2_h2(uint32_t x) {
    uint32_t r;
    asm("ex2.approx.f16x2 %0, %1;" : "=r"(r) : "r"(x));
    return r;
}
#define CP16(dst, src) \
    asm volatile("cp.async.cg.shared.global [%0], [%1], 16;" \
                 :: "r"(dst), "l"(src) : "memory")
#define CP_COMMIT() asm volatile("cp.async.commit_group;" ::: "memory")
#define CP_WAIT1()  asm volatile("cp.async.wait_group 1;"  ::: "memory")

// ---------------------------------------------------------------------------
// One-time weight conversion: [Wq|Wk|Wv] fp32 -> g_Wh fp16 (192 x 1024)
// ---------------------------------------------------------------------------
__global__ void wconv_kernel(const float* __restrict__ Wk,
                             const float* __restrict__ Wq,
                             const float* __restrict__ Wv)
{
    const int r = blockIdx.x;
    const float* src = (r < 64) ? (Wq + r * CC)
                     : (r < 128) ? (Wk + (r - 64) * CC)
                                 : (Wv + (r - 128) * CC);
    const float4 v = ((const float4*)src)[threadIdx.x];
    uint2 u;
    u.x = pack_h2(v.x, v.y);
    u.y = pack_h2(v.z, v.w);
    ((uint2*)(g_Wh + (long)r * CC))[threadIdx.x] = u;
}

// ---------------------------------------------------------------------------
// Projection via HMMA (R5-proven version, unchanged). grid = 512 CTAs
// (64 X-rows each), 256 threads. Q output pre-scaled by (1/8)*log2(e).
// ---------------------------------------------------------------------------
__global__ __launch_bounds__(256, 2) void proj_kernel(const float* __restrict__ X)
{
    __shared__ __align__(16) __half Xs[64 * PS];
    __shared__ __align__(16) __half Ws[192 * PS];

    const int tid = threadIdx.x;
    const int w = tid >> 5, l = tid & 31;
    const int rw = w & 3;        // row group (16 rows)
    const int wg = w >> 2;       // n-tile half: nt 12*wg .. 12*wg+11
    const long row0 = (long)blockIdx.x * 64;
    const float SC = 0.18033688011112042f;  // (1/8) * log2(e)

    float acc[12][4];
#pragma unroll
    for (int nt = 0; nt < 12; nt++)
#pragma unroll
        for (int c = 0; c < 4; c++) acc[nt][c] = 0.f;

    const uint32_t xs = smem_u32(Xs), ws = smem_u32(Ws);

    for (int c0 = 0; c0 < CC; c0 += 64) {
#pragma unroll
        for (int i = 0; i < 4; i++) {
            const int idx = tid + i * 256;       // 0..1023
            const int r = idx >> 4, c4 = idx & 15;
            const float4 v = *(const float4*)(X + (row0 + r) * CC + c0 + c4 * 4);
            uint2 u;
            u.x = pack_h2(v.x, v.y);
            u.y = pack_h2(v.z, v.w);
            *(uint2*)(&Xs[r * PS + c4 * 4]) = u;
        }
#pragma unroll
        for (int i = 0; i < 6; i++) {
            const int idx = tid + i * 256;       // 0..1535
            const int r = idx >> 3, c = idx & 7;
            *(uint4*)(&Ws[r * PS + c * 8]) =
                *(const uint4*)(g_Wh + (long)r * CC + c0 + c * 8);
        }
        __syncthreads();

        uint32_t aq[4][4];
#pragma unroll
        for (int ks = 0; ks < 4; ks++)
            ldsm_x4(aq[ks], xs + ((rw * 16 + (l & 15)) * PS + ks * 16 + (l >> 4) * 8) * 2);

#pragma unroll
        for (int nt = 0; nt < 12; nt++) {
            const int nta = wg * 12 + nt;
            uint32_t bf[8];
            const uint32_t base = ws + ((nta * 8 + (l & 7)) * PS + (l >> 3) * 8) * 2;
            ldsm_x4(bf, base);
            ldsm_x4(bf + 4, base + 64);
            mma16816(acc[nt], aq[0], bf);
            mma16816(acc[nt], aq[1], bf + 2);
            mma16816(acc[nt], aq[2], bf + 4);
            mma16816(acc[nt], aq[3], bf + 6);
        }
        __syncthreads();
    }

    const int r0 = rw * 16 + (l >> 2);
    const long gr0 = row0 + r0, gr1 = gr0 + 8;
    const int cb = 2 * (l & 3);
#pragma unroll
    for (int nt = 0; nt < 12; nt++) {
        const int nta = wg * 12 + nt;
        __half* dst = (nta < 8) ? g_Qh : (nta < 16) ? g_Kh : g_Vh;
        const float sc = (nta < 8) ? SC : 1.0f;
        const int col = (nta & 7) * 8 + cb;
        *(uint32_t*)(dst + gr0 * DD + col) = pack_h2(acc[nt][0] * sc, acc[nt][1] * sc);
        *(uint32_t*)(dst + gr1 * DD + col) = pack_h2(acc[nt][2] * sc, acc[nt][3] * sc);
    }
}

// ---------------------------------------------------------------------------
// Flash attention via HMMA: 128 threads (4 warps), each warp owns 32 Q rows
// (two m16 rowsets) -> every K/V fragment ldsm feeds 2x the mma, halving
// smem crossbar traffic (the measured bottleneck). 2 CTAs/SM.
// cp.async double-buffered K/V, f16x2 softmax, row-sums via ones-column.
// ---------------------------------------------------------------------------
__global__ __launch_bounds__(128, 2) void attn_kernel(float* __restrict__ out)
{
    extern __shared__ __align__(16) __half sm[];
    // bytes: K0 [0,18432) K1 [18432,36864) V0 [36864,55296) V1 [55296,73728)

    const int tid = threadIdx.x;
    const int w = tid >> 5, l = tid & 31;

    // Snake work mapping: heavy-first, bids k and 403-k (same SM) balance.
    const int bid  = blockIdx.x;
    const int item = (bid < 148) ? bid : (403 - bid);
    const int qt   = 31 - (item >> 3);
    const int b    = item & 7;

    const uint32_t base = smem_u32(sm);
    const uint32_t kbuf[2] = {base, base + 18432};
    const uint32_t vbuf[2] = {base + 36864, base + 55296};

    const __half* Kg0 = g_Kh + (long)b * TT * DD;
    const __half* Vg0 = g_Vh + (long)b * TT * DD;

    // ---- Load Q tile into K0 region; init ones-column in V buffers ----
    const __half* Qg = g_Qh + ((long)b * TT + (long)qt * 128) * DD;
#pragma unroll
    for (int i = 0; i < 8; i++) {
        const int idx = tid + i * 128;
        const int r = idx >> 3, c = idx & 7;
        *(uint4*)(&sm[r * PS + c * 8]) = *(const uint4*)(Qg + r * DD + c * 8);
    }
    {   // V cols 64..71: col 64 = 1.0, rest 0 (cp.async never touches these)
        __half ones[8] = {__float2half(1.f), __float2half(0.f), __float2half(0.f),
                          __float2half(0.f), __float2half(0.f), __float2half(0.f),
                          __float2half(0.f), __float2half(0.f)};
        *(uint4*)((char*)sm + vbuf[0] - base + (tid * PS + 64) * 2) = *(uint4*)ones;
        *(uint4*)((char*)sm + vbuf[1] - base + (tid * PS + 64) * 2) = *(uint4*)ones;
    }
    __syncthreads();
    uint32_t aq[2][4][4];   // [rowset][kstep][frag]
#pragma unroll
    for (int rs = 0; rs < 2; rs++)
#pragma unroll
        for (int ks = 0; ks < 4; ks++)
            ldsm_x4(aq[rs][ks],
                    base + ((w * 32 + rs * 16 + (l & 15)) * PS + ks * 16 + (l >> 4) * 8) * 2);
    __syncthreads();

    // ---- Prologue: async load tile 0 ----
#pragma unroll
    for (int i = 0; i < 8; i++) {
        const int idx = tid + i * 128;
        const int r = idx >> 3, c = idx & 7;
        const uint32_t off = (uint32_t)(r * PS + c * 8) * 2;
        CP16(kbuf[0] + off, Kg0 + r * DD + c * 8);
        CP16(vbuf[0] + off, Vg0 + r * DD + c * 8);
    }
    CP_COMMIT();

    float oacc[2][8][4];
#pragma unroll
    for (int rs = 0; rs < 2; rs++)
#pragma unroll
        for (int nt = 0; nt < 8; nt++)
#pragma unroll
            for (int c = 0; c < 4; c++) oacc[rs][nt][c] = 0.f;
    float oln[2][4] = {{0.f, 0.f, 0.f, 0.f}, {0.f, 0.f, 0.f, 0.f}};

    const int r0 = w * 32 + (l >> 2);   // rowset0 row (rowset1 = +16)
    const int cb = 2 * (l & 3);

    for (int kt = 0; kt <= qt; kt++) {
        const int p = kt & 1;
        // Issue next tile into the other buffer, then wait for current.
        if (kt < qt) {
            const __half* Kg = Kg0 + (long)(kt + 1) * 128 * DD;
            const __half* Vg = Vg0 + (long)(kt + 1) * 128 * DD;
#pragma unroll
            for (int i = 0; i < 8; i++) {
                const int idx = tid + i * 128;
                const int r = idx >> 3, c = idx & 7;
                const uint32_t off = (uint32_t)(r * PS + c * 8) * 2;
                CP16(kbuf[p ^ 1] + off, Kg + r * DD + c * 8);
                CP16(vbuf[p ^ 1] + off, Vg + r * DD + c * 8);
            }
        }
        CP_COMMIT();
        CP_WAIT1();
        __syncthreads();

        const uint32_t kcur = kbuf[p], vcur = vbuf[p];
        const bool diag = (kt == qt);

        // ---- S = Q.K^T (pre-scaled) -> mask -> pack -> ex2.f16x2 = P ----
        uint32_t pa[2][8][4];
#pragma unroll
        for (int i = 0; i < 8; i++) {
#pragma unroll
            for (int h = 0; h < 2; h++) {
                const int nt = 2 * i + h;
                uint32_t bf[8];
                const uint32_t kb = kcur + ((nt * 8 + (l & 7)) * PS + (l >> 3) * 8) * 2;
                ldsm_x4(bf, kb);
                ldsm_x4(bf + 4, kb + 64);

                float s4[2][4] = {{0.f, 0.f, 0.f, 0.f}, {0.f, 0.f, 0.f, 0.f}};
                mma16816(s4[0], aq[0][0], bf);
                mma16816(s4[1], aq[1][0], bf);
                mma16816(s4[0], aq[0][1], bf + 2);
                mma16816(s4[1], aq[1][1], bf + 2);
                mma16816(s4[0], aq[0][2], bf + 4);
                mma16816(s4[1], aq[1][2], bf + 4);
                mma16816(s4[0], aq[0][3], bf + 6);
                mma16816(s4[1], aq[1][3], bf + 6);

#pragma unroll
                for (int rs = 0; rs < 2; rs++) {
                    if (diag) {
                        const int rr = r0 + rs * 16;
                        const int col = nt * 8 + cb;
                        if (col     > rr)     s4[rs][0] = -30000.f;
                        if (col + 1 > rr)     s4[rs][1] = -30000.f;
                        if (col     > rr + 8) s4[rs][2] = -30000.f;
                        if (col + 1 > rr + 8) s4[rs][3] = -30000.f;
                    }
                    pa[rs][i][2 * h + 0] = ex2_h2(pack_h2(s4[rs][0], s4[rs][1]));
                    pa[rs][i][2 * h + 1] = ex2_h2(pack_h2(s4[rs][2], s4[rs][3]));
                }
            }
        }

        // ---- O += P . [V | 1] ----
#pragma unroll
        for (int ks2 = 0; ks2 < 4; ks2++) {
            uint32_t obf[4];
            ldsm_x4_t(obf, vcur + ((ks2 * 32 + l) * PS + 64) * 2);
#pragma unroll
            for (int ksh = 0; ksh < 2; ksh++) {
                const int ks = 2 * ks2 + ksh;
#pragma unroll
                for (int nv = 0; nv < 4; nv++) {
                    uint32_t bf[4];
                    ldsm_x4_t(bf, vcur + ((ks * 16 + (l & 15)) * PS + nv * 16 + (l >> 4) * 8) * 2);
                    mma16816(oacc[0][2 * nv],     pa[0][ks], bf);
                    mma16816(oacc[1][2 * nv],     pa[1][ks], bf);
                    mma16816(oacc[0][2 * nv + 1], pa[0][ks], bf + 2);
                    mma16816(oacc[1][2 * nv + 1], pa[1][ks], bf + 2);
                }
                mma16816(oln[0], pa[0][ks], obf + ksh * 2);
                mma16816(oln[1], pa[1][ks], obf + ksh * 2);
            }
        }
        __syncthreads();
    }

    // ---- epilogue: broadcast row sums from ones-column, normalize, store ----
    float* O = out + ((long)b * TT + (long)qt * 128) * DD;
#pragma unroll
    for (int rs = 0; rs < 2; rs++) {
        const float l0 = __shfl_sync(0xffffffffu, oln[rs][0], l & ~3);
        const float l1 = __shfl_sync(0xffffffffu, oln[rs][2], l & ~3);
        const float inv0 = 1.0f / l0;
        const float inv1 = 1.0f / l1;
        const long gr = (long)(r0 + rs * 16);
#pragma unroll
        for (int nt = 0; nt < 8; nt++) {
            const int col = nt * 8 + cb;
            float2 v0, v1;
            v0.x = oacc[rs][nt][0] * inv0; v0.y = oacc[rs][nt][1] * inv0;
            v1.x = oacc[rs][nt][2] * inv1; v1.y = oacc[rs][nt][3] * inv1;
            *(float2*)(O + gr * DD + col)       = v0;
            *(float2*)(O + (gr + 8) * DD + col) = v1;
        }
    }
}

// ---------------------------------------------------------------------------
extern "C" void kernel_launch(void* const* d_in, const int* in_sizes, int n_in,
                              void* d_out, int out_size)
{
    const float* X  = (const float*)d_in[0];
    const float* Wk = (const float*)d_in[1];
    const float* Wq = (const float*)d_in[2];
    const float* Wv = (const float*)d_in[3];
    float* out = (float*)d_out;

    cudaFuncSetAttribute(attn_kernel,
                         cudaFuncAttributeMaxDynamicSharedMemorySize, 73728);

    wconv_kernel<<<192, 256>>>(Wk, Wq, Wv);
    proj_kernel<<<(BB * TT) / 64, 256>>>(X);
    attn_kernel<<<256, 128, 73728>>>(out);
}

// round 15
// speedup vs baseline: 1.0061x; 1.0061x over previous
#include <cuda_runtime.h>
#include <cuda_fp16.h>
#include <stdint.h>

// Problem constants
#define BB 8
#define TT 4096
#define CC 1024
#define DD 64

#define PS 72  // padded smem row stride (halves): 144B -> conflict-free ldmatrix

// Projected tensors (fp16), row-major [b*T + t][d]. Q is pre-scaled by
// (1/8)*log2(e) so softmax is exp2 of the raw S accumulator.
__device__ __align__(16) __half g_Qh[BB * TT * DD];
__device__ __align__(16) __half g_Kh[BB * TT * DD];
__device__ __align__(16) __half g_Vh[BB * TT * DD];
// Fused weights fp16: rows 0-63 Wq, 64-127 Wk, 128-191 Wv
__device__ __align__(16) __half g_Wh[192 * CC];

// ---------------------------------------------------------------------------
// Warp-mma + cp.async helpers (sm_80+ ISA: works on base sm_103 target)
// ---------------------------------------------------------------------------
__device__ __forceinline__ uint32_t smem_u32(const void* p) {
    uint32_t a;
    asm("{ .reg .u64 t; cvta.to.shared.u64 t, %1; cvt.u32.u64 %0, t; }"
        : "=r"(a) : "l"(p));
    return a;
}
__device__ __forceinline__ void ldsm_x4(uint32_t* r, uint32_t a) {
    asm volatile("ldmatrix.sync.aligned.m8n8.x4.shared.b16 {%0,%1,%2,%3}, [%4];"
                 : "=r"(r[0]), "=r"(r[1]), "=r"(r[2]), "=r"(r[3]) : "r"(a));
}
__device__ __forceinline__ void ldsm_x4_t(uint32_t* r, uint32_t a) {
    asm volatile("ldmatrix.sync.aligned.m8n8.x4.trans.shared.b16 {%0,%1,%2,%3}, [%4];"
                 : "=r"(r[0]), "=r"(r[1]), "=r"(r[2]), "=r"(r[3]) : "r"(a));
}
__device__ __forceinline__ void mma16816(float* c, const uint32_t* a, const uint32_t* b) {
    asm volatile(
        "mma.sync.aligned.m16n8k16.row.col.f32.f16.f16.f32 "
        "{%0,%1,%2,%3}, {%4,%5,%6,%7}, {%8,%9}, {%0,%1,%2,%3};"
        : "+f"(c[0]), "+f"(c[1]), "+f"(c[2]), "+f"(c[3])
        : "r"(a[0]), "r"(a[1]), "r"(a[2]), "r"(a[3]), "r"(b[0]), "r"(b[1]));
}
__device__ __forceinline__ uint32_t pack_h2(float a, float b) {
    __half2 h = __floats2half2_rn(a, b);
    return *(uint32_t*)&h;
}
__device__ __forceinline__ uint32_t ex2_h2(uint32_t x) {
    uint32_t r;
    asm("ex2.approx.f16x2 %0, %1;" : "=r"(r) : "r"(x));
    return r;
}
#define CP16(dst, src) \
    asm volatile("cp.async.cg.shared.global [%0], [%1], 16;" \
                 :: "r"(dst), "l"(src) : "memory")
#define CP_COMMIT() asm volatile("cp.async.commit_group;" ::: "memory")
#define CP_WAIT1()  asm volatile("cp.async.wait_group 1;"  ::: "memory")

// ---------------------------------------------------------------------------
// One-time weight conversion: [Wq|Wk|Wv] fp32 -> g_Wh fp16 (192 x 1024)
// ---------------------------------------------------------------------------
__global__ void wconv_kernel(const float* __restrict__ Wk,
                             const float* __restrict__ Wq,
                             const float* __restrict__ Wv)
{
    const int r = blockIdx.x;
    const float* src = (r < 64) ? (Wq + r * CC)
                     : (r < 128) ? (Wk + (r - 64) * CC)
                                 : (Wv + (r - 128) * CC);
    const float4 v = ((const float4*)src)[threadIdx.x];
    uint2 u;
    u.x = pack_h2(v.x, v.y);
    u.y = pack_h2(v.z, v.w);
    ((uint2*)(g_Wh + (long)r * CC))[threadIdx.x] = u;
}

// ---------------------------------------------------------------------------
// Projection via HMMA (R5-proven version, unchanged). grid = 512 CTAs
// (64 X-rows each), 256 threads. Q output pre-scaled by (1/8)*log2(e).
// ---------------------------------------------------------------------------
__global__ __launch_bounds__(256, 2) void proj_kernel(const float* __restrict__ X)
{
    __shared__ __align__(16) __half Xs[64 * PS];
    __shared__ __align__(16) __half Ws[192 * PS];

    const int tid = threadIdx.x;
    const int w = tid >> 5, l = tid & 31;
    const int rw = w & 3;        // row group (16 rows)
    const int wg = w >> 2;       // n-tile half: nt 12*wg .. 12*wg+11
    const long row0 = (long)blockIdx.x * 64;
    const float SC = 0.18033688011112042f;  // (1/8) * log2(e)

    float acc[12][4];
#pragma unroll
    for (int nt = 0; nt < 12; nt++)
#pragma unroll
        for (int c = 0; c < 4; c++) acc[nt][c] = 0.f;

    const uint32_t xs = smem_u32(Xs), ws = smem_u32(Ws);

    for (int c0 = 0; c0 < CC; c0 += 64) {
#pragma unroll
        for (int i = 0; i < 4; i++) {
            const int idx = tid + i * 256;       // 0..1023
            const int r = idx >> 4, c4 = idx & 15;
            const float4 v = *(const float4*)(X + (row0 + r) * CC + c0 + c4 * 4);
            uint2 u;
            u.x = pack_h2(v.x, v.y);
            u.y = pack_h2(v.z, v.w);
            *(uint2*)(&Xs[r * PS + c4 * 4]) = u;
        }
#pragma unroll
        for (int i = 0; i < 6; i++) {
            const int idx = tid + i * 256;       // 0..1535
            const int r = idx >> 3, c = idx & 7;
            *(uint4*)(&Ws[r * PS + c * 8]) =
                *(const uint4*)(g_Wh + (long)r * CC + c0 + c * 8);
        }
        __syncthreads();

        uint32_t aq[4][4];
#pragma unroll
        for (int ks = 0; ks < 4; ks++)
            ldsm_x4(aq[ks], xs + ((rw * 16 + (l & 15)) * PS + ks * 16 + (l >> 4) * 8) * 2);

#pragma unroll
        for (int nt = 0; nt < 12; nt++) {
            const int nta = wg * 12 + nt;
            uint32_t bf[8];
            const uint32_t base = ws + ((nta * 8 + (l & 7)) * PS + (l >> 3) * 8) * 2;
            ldsm_x4(bf, base);
            ldsm_x4(bf + 4, base + 64);
            mma16816(acc[nt], aq[0], bf);
            mma16816(acc[nt], aq[1], bf + 2);
            mma16816(acc[nt], aq[2], bf + 4);
            mma16816(acc[nt], aq[3], bf + 6);
        }
        __syncthreads();
    }

    const int r0 = rw * 16 + (l >> 2);
    const long gr0 = row0 + r0, gr1 = gr0 + 8;
    const int cb = 2 * (l & 3);
#pragma unroll
    for (int nt = 0; nt < 12; nt++) {
        const int nta = wg * 12 + nt;
        __half* dst = (nta < 8) ? g_Qh : (nta < 16) ? g_Kh : g_Vh;
        const float sc = (nta < 8) ? SC : 1.0f;
        const int col = (nta & 7) * 8 + cb;
        *(uint32_t*)(dst + gr0 * DD + col) = pack_h2(acc[nt][0] * sc, acc[nt][1] * sc);
        *(uint32_t*)(dst + gr1 * DD + col) = pack_h2(acc[nt][2] * sc, acc[nt][3] * sc);
    }
}

// ---------------------------------------------------------------------------
// Flash attention via HMMA: 128 threads (4 warps), each warp owns 32 Q rows
// (two m16 rowsets) -> every K/V fragment ldsm feeds 2x the mma, halving
// smem crossbar traffic (the measured bottleneck). 2 CTAs/SM.
// cp.async double-buffered K/V, f16x2 softmax, row-sums via ones-column.
// ---------------------------------------------------------------------------
__global__ __launch_bounds__(128, 2) void attn_kernel(float* __restrict__ out)
{
    extern __shared__ __align__(16) __half sm[];
    // bytes: K0 [0,18432) K1 [18432,36864) V0 [36864,55296) V1 [55296,73728)

    const int tid = threadIdx.x;
    const int w = tid >> 5, l = tid & 31;

    // Snake work mapping: heavy-first, bids k and 403-k (same SM) balance.
    const int bid  = blockIdx.x;
    const int item = (bid < 148) ? bid : (403 - bid);
    const int qt   = 31 - (item >> 3);
    const int b    = item & 7;

    const uint32_t base = smem_u32(sm);
    const uint32_t kbuf[2] = {base, base + 18432};
    const uint32_t vbuf[2] = {base + 36864, base + 55296};

    const __half* Kg0 = g_Kh + (long)b * TT * DD;
    const __half* Vg0 = g_Vh + (long)b * TT * DD;

    // ---- Load Q tile into K0 region; init ones-column in V buffers ----
    const __half* Qg = g_Qh + ((long)b * TT + (long)qt * 128) * DD;
#pragma unroll
    for (int i = 0; i < 8; i++) {
        const int idx = tid + i * 128;
        const int r = idx >> 3, c = idx & 7;
        *(uint4*)(&sm[r * PS + c * 8]) = *(const uint4*)(Qg + r * DD + c * 8);
    }
    {   // V cols 64..71: col 64 = 1.0, rest 0 (cp.async never touches these)
        __half ones[8] = {__float2half(1.f), __float2half(0.f), __float2half(0.f),
                          __float2half(0.f), __float2half(0.f), __float2half(0.f),
                          __float2half(0.f), __float2half(0.f)};
        *(uint4*)((char*)sm + vbuf[0] - base + (tid * PS + 64) * 2) = *(uint4*)ones;
        *(uint4*)((char*)sm + vbuf[1] - base + (tid * PS + 64) * 2) = *(uint4*)ones;
    }
    __syncthreads();
    uint32_t aq[2][4][4];   // [rowset][kstep][frag]
#pragma unroll
    for (int rs = 0; rs < 2; rs++)
#pragma unroll
        for (int ks = 0; ks < 4; ks++)
            ldsm_x4(aq[rs][ks],
                    base + ((w * 32 + rs * 16 + (l & 15)) * PS + ks * 16 + (l >> 4) * 8) * 2);
    __syncthreads();

    // ---- Prologue: async load tile 0 ----
#pragma unroll
    for (int i = 0; i < 8; i++) {
        const int idx = tid + i * 128;
        const int r = idx >> 3, c = idx & 7;
        const uint32_t off = (uint32_t)(r * PS + c * 8) * 2;
        CP16(kbuf[0] + off, Kg0 + r * DD + c * 8);
        CP16(vbuf[0] + off, Vg0 + r * DD + c * 8);
    }
    CP_COMMIT();

    float oacc[2][8][4];
#pragma unroll
    for (int rs = 0; rs < 2; rs++)
#pragma unroll
        for (int nt = 0; nt < 8; nt++)
#pragma unroll
            for (int c = 0; c < 4; c++) oacc[rs][nt][c] = 0.f;
    float oln[2][4] = {{0.f, 0.f, 0.f, 0.f}, {0.f, 0.f, 0.f, 0.f}};

    const int r0 = w * 32 + (l >> 2);   // rowset0 row (rowset1 = +16)
    const int cb = 2 * (l & 3);

    for (int kt = 0; kt <= qt; kt++) {
        const int p = kt & 1;
        // Issue next tile into the other buffer, then wait for current.
        if (kt < qt) {
            const __half* Kg = Kg0 + (long)(kt + 1) * 128 * DD;
            const __half* Vg = Vg0 + (long)(kt + 1) * 128 * DD;
#pragma unroll
            for (int i = 0; i < 8; i++) {
                const int idx = tid + i * 128;
                const int r = idx >> 3, c = idx & 7;
                const uint32_t off = (uint32_t)(r * PS + c * 8) * 2;
                CP16(kbuf[p ^ 1] + off, Kg + r * DD + c * 8);
                CP16(vbuf[p ^ 1] + off, Vg + r * DD + c * 8);
            }
        }
        CP_COMMIT();
        CP_WAIT1();
        __syncthreads();

        const uint32_t kcur = kbuf[p], vcur = vbuf[p];
        const bool diag = (kt == qt);

        // ---- S = Q.K^T (pre-scaled) -> mask -> pack -> ex2.f16x2 = P ----
        uint32_t pa[2][8][4];
#pragma unroll
        for (int i = 0; i < 8; i++) {
#pragma unroll
            for (int h = 0; h < 2; h++) {
                const int nt = 2 * i + h;
                uint32_t bf[8];
                const uint32_t kb = kcur + ((nt * 8 + (l & 7)) * PS + (l >> 3) * 8) * 2;
                ldsm_x4(bf, kb);
                ldsm_x4(bf + 4, kb + 64);

                float s4[2][4] = {{0.f, 0.f, 0.f, 0.f}, {0.f, 0.f, 0.f, 0.f}};
                mma16816(s4[0], aq[0][0], bf);
                mma16816(s4[1], aq[1][0], bf);
                mma16816(s4[0], aq[0][1], bf + 2);
                mma16816(s4[1], aq[1][1], bf + 2);
                mma16816(s4[0], aq[0][2], bf + 4);
                mma16816(s4[1], aq[1][2], bf + 4);
                mma16816(s4[0], aq[0][3], bf + 6);
                mma16816(s4[1], aq[1][3], bf + 6);

#pragma unroll
                for (int rs = 0; rs < 2; rs++) {
                    if (diag) {
                        const int rr = r0 + rs * 16;
                        const int col = nt * 8 + cb;
                        if (col     > rr)     s4[rs][0] = -30000.f;
                        if (col + 1 > rr)     s4[rs][1] = -30000.f;
                        if (col     > rr + 8) s4[rs][2] = -30000.f;
                        if (col + 1 > rr + 8) s4[rs][3] = -30000.f;
                    }
                    pa[rs][i][2 * h + 0] = ex2_h2(pack_h2(s4[rs][0], s4[rs][1]));
                    pa[rs][i][2 * h + 1] = ex2_h2(pack_h2(s4[rs][2], s4[rs][3]));
                }
            }
        }

        // ---- O += P . [V | 1] ----
#pragma unroll
        for (int ks2 = 0; ks2 < 4; ks2++) {
            uint32_t obf[4];
            ldsm_x4_t(obf, vcur + ((ks2 * 32 + l) * PS + 64) * 2);
#pragma unroll
            for (int ksh = 0; ksh < 2; ksh++) {
                const int ks = 2 * ks2 + ksh;
#pragma unroll
                for (int nv = 0; nv < 4; nv++) {
                    uint32_t bf[4];
                    ldsm_x4_t(bf, vcur + ((ks * 16 + (l & 15)) * PS + nv * 16 + (l >> 4) * 8) * 2);
                    mma16816(oacc[0][2 * nv],     pa[0][ks], bf);
                    mma16816(oacc[1][2 * nv],     pa[1][ks], bf);
                    mma16816(oacc[0][2 * nv + 1], pa[0][ks], bf + 2);
                    mma16816(oacc[1][2 * nv + 1], pa[1][ks], bf + 2);
                }
                mma16816(oln[0], pa[0][ks], obf + ksh * 2);
                mma16816(oln[1], pa[1][ks], obf + ksh * 2);
            }
        }
        __syncthreads();
    }

    // ---- epilogue: broadcast row sums from ones-column, normalize, store ----
    float* O = out + ((long)b * TT + (long)qt * 128) * DD;
#pragma unroll
    for (int rs = 0; rs < 2; rs++) {
        const float l0 = __shfl_sync(0xffffffffu, oln[rs][0], l & ~3);
        const float l1 = __shfl_sync(0xffffffffu, oln[rs][2], l & ~3);
        const float inv0 = 1.0f / l0;
        const float inv1 = 1.0f / l1;
        const long gr = (long)(r0 + rs * 16);
#pragma unroll
        for (int nt = 0; nt < 8; nt++) {
            const int col = nt * 8 + cb;
            float2 v0, v1;
            v0.x = oacc[rs][nt][0] * inv0; v0.y = oacc[rs][nt][1] * inv0;
            v1.x = oacc[rs][nt][2] * inv1; v1.y = oacc[rs][nt][3] * inv1;
            *(float2*)(O + gr * DD + col)       = v0;
            *(float2*)(O + (gr + 8) * DD + col) = v1;
        }
    }
}

// ---------------------------------------------------------------------------
extern "C" void kernel_launch(void* const* d_in, const int* in_sizes, int n_in,
                              void* d_out, int out_size)
{
    const float* X  = (const float*)d_in[0];
    const float* Wk = (const float*)d_in[1];
    const float* Wq = (const float*)d_in[2];
    const float* Wv = (const float*)d_in[3];
    float* out = (float*)d_out;

    cudaFuncSetAttribute(attn_kernel,
                         cudaFuncAttributeMaxDynamicSharedMemorySize, 73728);

    wconv_kernel<<<192, 256>>>(Wk, Wq, Wv);
    proj_kernel<<<(BB * TT) / 64, 256>>>(X);
    attn_kernel<<<256, 128, 73728>>>(out);
}

// round 16
// speedup vs baseline: 1.0063x; 1.0002x over previous
#include <cuda_runtime.h>
#include <cuda_fp16.h>
#include <stdint.h>

// Problem constants
#define BB 8
#define TT 4096
#define CC 1024
#define DD 64

#define PS 72  // padded smem row stride (halves): 144B -> conflict-free ldmatrix

// Projected tensors (fp16), row-major [b*T + t][d]. Q is pre-scaled by
// (1/8)*log2(e) so softmax is exp2 of the raw S accumulator.
__device__ __align__(16) __half g_Qh[BB * TT * DD];
__device__ __align__(16) __half g_Kh[BB * TT * DD];
__device__ __align__(16) __half g_Vh[BB * TT * DD];
// Fused weights fp16: rows 0-63 Wq, 64-127 Wk, 128-191 Wv
__device__ __align__(16) __half g_Wh[192 * CC];

// ---------------------------------------------------------------------------
// Warp-mma + cp.async helpers (sm_80+ ISA: works on base sm_103 target)
// ---------------------------------------------------------------------------
__device__ __forceinline__ uint32_t smem_u32(const void* p) {
    uint32_t a;
    asm("{ .reg .u64 t; cvta.to.shared.u64 t, %1; cvt.u32.u64 %0, t; }"
        : "=r"(a) : "l"(p));
    return a;
}
__device__ __forceinline__ void ldsm_x4(uint32_t* r, uint32_t a) {
    asm volatile("ldmatrix.sync.aligned.m8n8.x4.shared.b16 {%0,%1,%2,%3}, [%4];"
                 : "=r"(r[0]), "=r"(r[1]), "=r"(r[2]), "=r"(r[3]) : "r"(a));
}
__device__ __forceinline__ void ldsm_x4_t(uint32_t* r, uint32_t a) {
    asm volatile("ldmatrix.sync.aligned.m8n8.x4.trans.shared.b16 {%0,%1,%2,%3}, [%4];"
                 : "=r"(r[0]), "=r"(r[1]), "=r"(r[2]), "=r"(r[3]) : "r"(a));
}
__device__ __forceinline__ void mma16816(float* c, const uint32_t* a, const uint32_t* b) {
    asm volatile(
        "mma.sync.aligned.m16n8k16.row.col.f32.f16.f16.f32 "
        "{%0,%1,%2,%3}, {%4,%5,%6,%7}, {%8,%9}, {%0,%1,%2,%3};"
        : "+f"(c[0]), "+f"(c[1]), "+f"(c[2]), "+f"(c[3])
        : "r"(a[0]), "r"(a[1]), "r"(a[2]), "r"(a[3]), "r"(b[0]), "r"(b[1]));
}
__device__ __forceinline__ uint32_t pack_h2(float a, float b) {
    __half2 h = __floats2half2_rn(a, b);
    return *(uint32_t*)&h;
}
__device__ __forceinline__ uint32_t ex2_h2(uint32_t x) {
    uint32_t r;
    asm("ex2.approx.f16x2 %0, %1;" : "=r"(r) : "r"(x));
    return r;
}
#define CP16(dst, src) \
    asm volatile("cp.async.cg.shared.global [%0], [%1], 16;" \
                 :: "r"(dst), "l"(src) : "memory")
#define CP_COMMIT() asm volatile("cp.async.commit_group;" ::: "memory")
#define CP_WAIT1()  asm volatile("cp.async.wait_group 1;"  ::: "memory")

// ---------------------------------------------------------------------------
// One-time weight conversion: [Wq|Wk|Wv] fp32 -> g_Wh fp16 (192 x 1024)
// ---------------------------------------------------------------------------
__global__ void wconv_kernel(const float* __restrict__ Wk,
                             const float* __restrict__ Wq,
                             const float* __restrict__ Wv)
{
    const int r = blockIdx.x;
    const float* src = (r < 64) ? (Wq + r * CC)
                     : (r < 128) ? (Wk + (r - 64) * CC)
                                 : (Wv + (r - 128) * CC);
    const float4 v = ((const float4*)src)[threadIdx.x];
    uint2 u;
    u.x = pack_h2(v.x, v.y);
    u.y = pack_h2(v.z, v.w);
    ((uint2*)(g_Wh + (long)r * CC))[threadIdx.x] = u;
}

// ---------------------------------------------------------------------------
// Projection via HMMA (R5-proven version, unchanged). grid = 512 CTAs
// (64 X-rows each), 256 threads. Q output pre-scaled by (1/8)*log2(e).
// ---------------------------------------------------------------------------
__global__ __launch_bounds__(256, 2) void proj_kernel(const float* __restrict__ X)
{
    __shared__ __align__(16) __half Xs[64 * PS];
    __shared__ __align__(16) __half Ws[192 * PS];

    const int tid = threadIdx.x;
    const int w = tid >> 5, l = tid & 31;
    const int rw = w & 3;        // row group (16 rows)
    const int wg = w >> 2;       // n-tile half: nt 12*wg .. 12*wg+11
    const long row0 = (long)blockIdx.x * 64;
    const float SC = 0.18033688011112042f;  // (1/8) * log2(e)

    float acc[12][4];
#pragma unroll
    for (int nt = 0; nt < 12; nt++)
#pragma unroll
        for (int c = 0; c < 4; c++) acc[nt][c] = 0.f;

    const uint32_t xs = smem_u32(Xs), ws = smem_u32(Ws);

    for (int c0 = 0; c0 < CC; c0 += 64) {
#pragma unroll
        for (int i = 0; i < 4; i++) {
            const int idx = tid + i * 256;       // 0..1023
            const int r = idx >> 4, c4 = idx & 15;
            const float4 v = *(const float4*)(X + (row0 + r) * CC + c0 + c4 * 4);
            uint2 u;
            u.x = pack_h2(v.x, v.y);
            u.y = pack_h2(v.z, v.w);
            *(uint2*)(&Xs[r * PS + c4 * 4]) = u;
        }
#pragma unroll
        for (int i = 0; i < 6; i++) {
            const int idx = tid + i * 256;       // 0..1535
            const int r = idx >> 3, c = idx & 7;
            *(uint4*)(&Ws[r * PS + c * 8]) =
                *(const uint4*)(g_Wh + (long)r * CC + c0 + c * 8);
        }
        __syncthreads();

        uint32_t aq[4][4];
#pragma unroll
        for (int ks = 0; ks < 4; ks++)
            ldsm_x4(aq[ks], xs + ((rw * 16 + (l & 15)) * PS + ks * 16 + (l >> 4) * 8) * 2);

#pragma unroll
        for (int nt = 0; nt < 12; nt++) {
            const int nta = wg * 12 + nt;
            uint32_t bf[8];
            const uint32_t base = ws + ((nta * 8 + (l & 7)) * PS + (l >> 3) * 8) * 2;
            ldsm_x4(bf, base);
            ldsm_x4(bf + 4, base + 64);
            mma16816(acc[nt], aq[0], bf);
            mma16816(acc[nt], aq[1], bf + 2);
            mma16816(acc[nt], aq[2], bf + 4);
            mma16816(acc[nt], aq[3], bf + 6);
        }
        __syncthreads();
    }

    const int r0 = rw * 16 + (l >> 2);
    const long gr0 = row0 + r0, gr1 = gr0 + 8;
    const int cb = 2 * (l & 3);
#pragma unroll
    for (int nt = 0; nt < 12; nt++) {
        const int nta = wg * 12 + nt;
        __half* dst = (nta < 8) ? g_Qh : (nta < 16) ? g_Kh : g_Vh;
        const float sc = (nta < 8) ? SC : 1.0f;
        const int col = (nta & 7) * 8 + cb;
        *(uint32_t*)(dst + gr0 * DD + col) = pack_h2(acc[nt][0] * sc, acc[nt][1] * sc);
        *(uint32_t*)(dst + gr1 * DD + col) = pack_h2(acc[nt][2] * sc, acc[nt][3] * sc);
    }
}

// ---------------------------------------------------------------------------
// Flash attention via HMMA: 128 threads (4 warps), each warp owns 32 Q rows
// (two m16 rowsets) -> every K/V fragment ldsm feeds 2x the mma, halving
// smem crossbar traffic (the measured bottleneck). 2 CTAs/SM.
// cp.async double-buffered K/V, f16x2 softmax, row-sums via ones-column.
// ---------------------------------------------------------------------------
__global__ __launch_bounds__(128, 2) void attn_kernel(float* __restrict__ out)
{
    extern __shared__ __align__(16) __half sm[];
    // bytes: K0 [0,18432) K1 [18432,36864) V0 [36864,55296) V1 [55296,73728)

    const int tid = threadIdx.x;
    const int w = tid >> 5, l = tid & 31;

    // Snake work mapping: heavy-first, bids k and 403-k (same SM) balance.
    const int bid  = blockIdx.x;
    const int item = (bid < 148) ? bid : (403 - bid);
    const int qt   = 31 - (item >> 3);
    const int b    = item & 7;

    const uint32_t base = smem_u32(sm);
    const uint32_t kbuf[2] = {base, base + 18432};
    const uint32_t vbuf[2] = {base + 36864, base + 55296};

    const __half* Kg0 = g_Kh + (long)b * TT * DD;
    const __half* Vg0 = g_Vh + (long)b * TT * DD;

    // ---- Load Q tile into K0 region; init ones-column in V buffers ----
    const __half* Qg = g_Qh + ((long)b * TT + (long)qt * 128) * DD;
#pragma unroll
    for (int i = 0; i < 8; i++) {
        const int idx = tid + i * 128;
        const int r = idx >> 3, c = idx & 7;
        *(uint4*)(&sm[r * PS + c * 8]) = *(const uint4*)(Qg + r * DD + c * 8);
    }
    {   // V cols 64..71: col 64 = 1.0, rest 0 (cp.async never touches these)
        __half ones[8] = {__float2half(1.f), __float2half(0.f), __float2half(0.f),
                          __float2half(0.f), __float2half(0.f), __float2half(0.f),
                          __float2half(0.f), __float2half(0.f)};
        *(uint4*)((char*)sm + vbuf[0] - base + (tid * PS + 64) * 2) = *(uint4*)ones;
        *(uint4*)((char*)sm + vbuf[1] - base + (tid * PS + 64) * 2) = *(uint4*)ones;
    }
    __syncthreads();
    uint32_t aq[2][4][4];   // [rowset][kstep][frag]
#pragma unroll
    for (int rs = 0; rs < 2; rs++)
#pragma unroll
        for (int ks = 0; ks < 4; ks++)
            ldsm_x4(aq[rs][ks],
                    base + ((w * 32 + rs * 16 + (l & 15)) * PS + ks * 16 + (l >> 4) * 8) * 2);
    __syncthreads();

    // ---- Prologue: async load tile 0 ----
#pragma unroll
    for (int i = 0; i < 8; i++) {
        const int idx = tid + i * 128;
        const int r = idx >> 3, c = idx & 7;
        const uint32_t off = (uint32_t)(r * PS + c * 8) * 2;
        CP16(kbuf[0] + off, Kg0 + r * DD + c * 8);
        CP16(vbuf[0] + off, Vg0 + r * DD + c * 8);
    }
    CP_COMMIT();

    float oacc[2][8][4];
#pragma unroll
    for (int rs = 0; rs < 2; rs++)
#pragma unroll
        for (int nt = 0; nt < 8; nt++)
#pragma unroll
            for (int c = 0; c < 4; c++) oacc[rs][nt][c] = 0.f;
    float oln[2][4] = {{0.f, 0.f, 0.f, 0.f}, {0.f, 0.f, 0.f, 0.f}};

    const int r0 = w * 32 + (l >> 2);   // rowset0 row (rowset1 = +16)
    const int cb = 2 * (l & 3);

    for (int kt = 0; kt <= qt; kt++) {
        const int p = kt & 1;
        // Issue next tile into the other buffer, then wait for current.
        if (kt < qt) {
            const __half* Kg = Kg0 + (long)(kt + 1) * 128 * DD;
            const __half* Vg = Vg0 + (long)(kt + 1) * 128 * DD;
#pragma unroll
            for (int i = 0; i < 8; i++) {
                const int idx = tid + i * 128;
                const int r = idx >> 3, c = idx & 7;
                const uint32_t off = (uint32_t)(r * PS + c * 8) * 2;
                CP16(kbuf[p ^ 1] + off, Kg + r * DD + c * 8);
                CP16(vbuf[p ^ 1] + off, Vg + r * DD + c * 8);
            }
        }
        CP_COMMIT();
        CP_WAIT1();
        __syncthreads();

        const uint32_t kcur = kbuf[p], vcur = vbuf[p];
        const bool diag = (kt == qt);

        // ---- S = Q.K^T (pre-scaled) -> mask -> pack -> ex2.f16x2 = P ----
        uint32_t pa[2][8][4];
#pragma unroll
        for (int i = 0; i < 8; i++) {
#pragma unroll
            for (int h = 0; h < 2; h++) {
                const int nt = 2 * i + h;
                uint32_t bf[8];
                const uint32_t kb = kcur + ((nt * 8 + (l & 7)) * PS + (l >> 3) * 8) * 2;
                ldsm_x4(bf, kb);
                ldsm_x4(bf + 4, kb + 64);

                float s4[2][4] = {{0.f, 0.f, 0.f, 0.f}, {0.f, 0.f, 0.f, 0.f}};
                mma16816(s4[0], aq[0][0], bf);
                mma16816(s4[1], aq[1][0], bf);
                mma16816(s4[0], aq[0][1], bf + 2);
                mma16816(s4[1], aq[1][1], bf + 2);
                mma16816(s4[0], aq[0][2], bf + 4);
                mma16816(s4[1], aq[1][2], bf + 4);
                mma16816(s4[0], aq[0][3], bf + 6);
                mma16816(s4[1], aq[1][3], bf + 6);

#pragma unroll
                for (int rs = 0; rs < 2; rs++) {
                    if (diag) {
                        const int rr = r0 + rs * 16;
                        const int col = nt * 8 + cb;
                        if (col     > rr)     s4[rs][0] = -30000.f;
                        if (col + 1 > rr)     s4[rs][1] = -30000.f;
                        if (col     > rr + 8) s4[rs][2] = -30000.f;
                        if (col + 1 > rr + 8) s4[rs][3] = -30000.f;
                    }
                    pa[rs][i][2 * h + 0] = ex2_h2(pack_h2(s4[rs][0], s4[rs][1]));
                    pa[rs][i][2 * h + 1] = ex2_h2(pack_h2(s4[rs][2], s4[rs][3]));
                }
            }
        }

        // ---- O += P . [V | 1] ----
#pragma unroll
        for (int ks2 = 0; ks2 < 4; ks2++) {
            uint32_t obf[4];
            ldsm_x4_t(obf, vcur + ((ks2 * 32 + l) * PS + 64) * 2);
#pragma unroll
            for (int ksh = 0; ksh < 2; ksh++) {
                const int ks = 2 * ks2 + ksh;
#pragma unroll
                for (int nv = 0; nv < 4; nv++) {
                    uint32_t bf[4];
                    ldsm_x4_t(bf, vcur + ((ks * 16 + (l & 15)) * PS + nv * 16 + (l >> 4) * 8) * 2);
                    mma16816(oacc[0][2 * nv],     pa[0][ks], bf);
                    mma16816(oacc[1][2 * nv],     pa[1][ks], bf);
                    mma16816(oacc[0][2 * nv + 1], pa[0][ks], bf + 2);
                    mma16816(oacc[1][2 * nv + 1], pa[1][ks], bf + 2);
                }
                mma16816(oln[0], pa[0][ks], obf + ksh * 2);
                mma16816(oln[1], pa[1][ks], obf + ksh * 2);
            }
        }
        __syncthreads();
    }

    // ---- epilogue: broadcast row sums from ones-column, normalize, store ----
    float* O = out + ((long)b * TT + (long)qt * 128) * DD;
#pragma unroll
    for (int rs = 0; rs < 2; rs++) {
        const float l0 = __shfl_sync(0xffffffffu, oln[rs][0], l & ~3);
        const float l1 = __shfl_sync(0xffffffffu, oln[rs][2], l & ~3);
        const float inv0 = 1.0f / l0;
        const float inv1 = 1.0f / l1;
        const long gr = (long)(r0 + rs * 16);
#pragma unroll
        for (int nt = 0; nt < 8; nt++) {
            const int col = nt * 8 + cb;
            float2 v0, v1;
            v0.x = oacc[rs][nt][0] * inv0; v0.y = oacc[rs][nt][1] * inv0;
            v1.x = oacc[rs][nt][2] * inv1; v1.y = oacc[rs][nt][3] * inv1;
            *(float2*)(O + gr * DD + col)       = v0;
            *(float2*)(O + (gr + 8) * DD + col) = v1;
        }
    }
}

// ---------------------------------------------------------------------------
extern "C" void kernel_launch(void* const* d_in, const int* in_sizes, int n_in,
                              void* d_out, int out_size)
{
    const float* X  = (const float*)d_in[0];
    const float* Wk = (const float*)d_in[1];
    const float* Wq = (const float*)d_in[2];
    const float* Wv = (const float*)d_in[3];
    float* out = (float*)d_out;

    cudaFuncSetAttribute(attn_kernel,
                         cudaFuncAttributeMaxDynamicSharedMemorySize, 73728);

    wconv_kernel<<<192, 256>>>(Wk, Wq, Wv);
    proj_kernel<<<(BB * TT) / 64, 256>>>(X);
    attn_kernel<<<256, 128, 73728>>>(out);
}